// round 8
// baseline (speedup 1.0000x reference)
#include <cuda_runtime.h>
#include <cstdint>

// Problem dims
#define DM 8192
#define DK 2048
#define DN 2048

// GEMM tiling: CTA 128x128, 8 warps in 4(M) x 2(N), warp tile 32x64. 2 CTAs/SM.
// A comes straight from global via LDG.32 fragments; only B goes through smem.
constexpr int TM = 128;
constexpr int TN = 128;
constexpr int TKC = 128;           // K bytes per pipeline stage (4 ks sub-chunks)
constexpr int ST = 4;              // pipeline stages (B only)
constexpr int NK = DK / TKC;       // 16 chunks

constexpr int ROWB = 144;          // 128 data + 16 pad -> conflict-free ldmatrix
constexpr int B_ST = TN * ROWB;    // 18432
constexpr int STAGE = B_ST;
constexpr int SMEM_BYTES = ST * STAGE; // 73728 -> 2 CTAs/SM

// s8 scratch (allocation-free __device__ globals)
__device__ int8_t g_A[(size_t)DM * DK];
__device__ int8_t g_B[(size_t)DN * DK];

// ---------------- helpers ----------------
__device__ __forceinline__ uint32_t smem_u32(const void* p) {
    uint32_t a;
    asm("{ .reg .u64 t; cvta.to.shared.u64 t, %1; cvt.u32.u64 %0, t; }" : "=r"(a) : "l"(p));
    return a;
}

__device__ __forceinline__ void ldm_x4(uint32_t* r, uint32_t addr) {
    asm volatile("ldmatrix.sync.aligned.m8n8.x4.shared.b16 {%0,%1,%2,%3}, [%4];"
                 : "=r"(r[0]), "=r"(r[1]), "=r"(r[2]), "=r"(r[3]) : "r"(addr));
}

#define CP_ASYNC16(dst_u32, src_ptr) \
    asm volatile("cp.async.cg.shared.global [%0], [%1], 16;" \
                 :: "r"((uint32_t)(dst_u32)), "l"(src_ptr) : "memory")
#define CP_COMMIT() asm volatile("cp.async.commit_group;" ::: "memory")
#define CP_WAIT2()  asm volatile("cp.async.wait_group 2;" ::: "memory")
#define CP_WAIT0()  asm volatile("cp.async.wait_group 0;" ::: "memory")

// s8 MMA: D(16x8,s32) += A(16x32,s8 row) * B(32x8,s8 col)
#define MMA_S8(C, A, B0, B1) \
    asm volatile("mma.sync.aligned.m16n8k32.row.col.s32.s8.s8.s32 " \
        "{%0,%1,%2,%3}, {%4,%5,%6,%7}, {%8,%9}, {%0,%1,%2,%3};" \
        : "+r"((C)[0]), "+r"((C)[1]), "+r"((C)[2]), "+r"((C)[3]) \
        : "r"((A)[0]), "r"((A)[1]), "r"((A)[2]), "r"((A)[3]), \
          "r"(B0), "r"(B1))

__device__ __forceinline__ float isgn(int v) {
    return (v > 0) ? 1.0f : ((v < 0) ? -1.0f : 0.0f);
}

// ---------------- conversion: fp32 (+-1) -> s8 (+-1), both tensors in one launch ----
constexpr int NA4 = DM * DK / 4;
constexpr int NW4 = DN * DK / 4;
__global__ void cvt_kernel(const float4* __restrict__ a, const float4* __restrict__ w) {
    int i = blockIdx.x * blockDim.x + threadIdx.x;
    const float4* src;
    uint32_t* dst;
    int idx;
    if (i < NA4) {
        src = a; dst = reinterpret_cast<uint32_t*>(g_A); idx = i;
    } else {
        idx = i - NA4;
        if (idx >= NW4) return;
        src = w; dst = reinterpret_cast<uint32_t*>(g_B);
    }
    float4 v = src[idx];
    uint32_t p = (uint32_t)(uint8_t)(int8_t)(v.x > 0.0f ? 1 : -1)
               | ((uint32_t)(uint8_t)(int8_t)(v.y > 0.0f ? 1 : -1) << 8)
               | ((uint32_t)(uint8_t)(int8_t)(v.z > 0.0f ? 1 : -1) << 16)
               | ((uint32_t)(uint8_t)(int8_t)(v.w > 0.0f ? 1 : -1) << 24);
    dst[idx] = p;
}

// ---------------- GEMM + sign kernel ----------------
__global__ void __launch_bounds__(256, 2) binlinear_gemm_kernel(float* __restrict__ out) {
    extern __shared__ int8_t smem[];
    const uint32_t sb = smem_u32(smem);
    const int tid = threadIdx.x;
    const int wid = tid >> 5;
    const int lane = tid & 31;
    const int g = lane >> 2;      // 0..7
    const int tig = lane & 3;     // 0..3
    const int m0 = blockIdx.y * TM;
    const int n0 = blockIdx.x * TN;
    const int wm = (wid & 3) * 32;     // warp M offset
    const int wn = (wid >> 2) * 64;    // warp N offset

    // B ldmatrix per-lane address offset (verified: ROWB=144 -> conflict-free)
    const uint32_t boff = (uint32_t)(wn + (lane >> 4) * 8 + (lane & 7)) * ROWB
                        + ((lane & 8) << 1);

    int c[2][8][4];
    #pragma unroll
    for (int mt = 0; mt < 2; ++mt)
        #pragma unroll
        for (int nt = 0; nt < 8; ++nt)
            #pragma unroll
            for (int r = 0; r < 4; ++r) c[mt][nt][r] = 0;

    // A fragment base pointer: this thread's k-contiguous 4B words.
    // a[mt][0] = A[wm+mt*16+g   ][k + tig*4]
    // a[mt][1] = A[wm+mt*16+g+8 ][k + tig*4]
    // a[mt][2] = A[wm+mt*16+g   ][k + tig*4 + 16]
    // a[mt][3] = A[wm+mt*16+g+8 ][k + tig*4 + 16]
    const int8_t* pA = g_A + (size_t)(m0 + wm + g) * DK + tig * 4;
    const int8_t* gBbase = g_B + (size_t)n0 * DK;

    auto load_a = [&](uint32_t (&a)[2][4], int kbyte) {
        #pragma unroll
        for (int mt = 0; mt < 2; ++mt) {
            const int8_t* pr = pA + (size_t)(mt * 16) * DK + kbyte;
            a[mt][0] = *reinterpret_cast<const uint32_t*>(pr);
            a[mt][1] = *reinterpret_cast<const uint32_t*>(pr + 8 * DK);
            a[mt][2] = *reinterpret_cast<const uint32_t*>(pr + 16);
            a[mt][3] = *reinterpret_cast<const uint32_t*>(pr + 8 * DK + 16);
        }
    };

    // per stage: B = 128 rows x 8 segs = 1024 16B-chunks (4/thread)
    auto load_stage = [&](int s, int kc) {
        const uint32_t Bb = sb + s * STAGE;
        const int8_t* gB = gBbase + kc * TKC;
        #pragma unroll
        for (int h = 0; h < 4; ++h) {
            int ch = tid + h * 256;
            int row = ch >> 3, seg = ch & 7;
            CP_ASYNC16(Bb + row * ROWB + seg * 16, gB + (size_t)row * DK + seg * 16);
        }
        CP_COMMIT();
    };

    // prologue: fill ST-1 stages
    #pragma unroll
    for (int s = 0; s < ST - 1; ++s) load_stage(s, s);

    for (int i = 0; i < NK; ++i) {
        if (i < NK - (ST - 1)) CP_WAIT2();
        else                   CP_WAIT0();
        __syncthreads();

        if (i + ST - 1 < NK) load_stage((i + ST - 1) % ST, i + ST - 1);

        const uint32_t Bb = sb + (i % ST) * STAGE;
        const int kb = i * TKC;

        uint32_t a0[2][4], a1[2][4];
        load_a(a0, kb);                          // ks 0
        #pragma unroll
        for (int ks = 0; ks < 4; ++ks) {
            uint32_t (&ac)[2][4] = (ks & 1) ? a1 : a0;
            uint32_t (&an)[2][4] = (ks & 1) ? a0 : a1;
            if (ks < 3) load_a(an, kb + (ks + 1) * 32);   // prefetch next ks
            const int k0 = ks * 32;
            #pragma unroll
            for (int p = 0; p < 4; ++p) {
                uint32_t t[4];
                ldm_x4(t, Bb + boff + p * 16 * ROWB + k0);
                MMA_S8(c[0][2 * p + 0], ac[0], t[0], t[1]);
                MMA_S8(c[0][2 * p + 1], ac[0], t[2], t[3]);
                MMA_S8(c[1][2 * p + 0], ac[1], t[0], t[1]);
                MMA_S8(c[1][2 * p + 1], ac[1], t[2], t[3]);
            }
        }
    }

    // ---- epilogue: sign -> float, 8B vectorized stores ----
    #pragma unroll
    for (int mt = 0; mt < 2; ++mt) {
        const int row0 = m0 + wm + mt * 16 + g;
        float* o0 = out + (size_t)row0 * DN + n0 + wn;
        float* o1 = out + (size_t)(row0 + 8) * DN + n0 + wn;
        #pragma unroll
        for (int nt = 0; nt < 8; ++nt) {
            const int col = nt * 8 + tig * 2;
            float2 v0 = make_float2(isgn(c[mt][nt][0]), isgn(c[mt][nt][1]));
            float2 v1 = make_float2(isgn(c[mt][nt][2]), isgn(c[mt][nt][3]));
            *reinterpret_cast<float2*>(o0 + col) = v0;
            *reinterpret_cast<float2*>(o1 + col) = v1;
        }
    }
}

// ---------------- launch ----------------
extern "C" void kernel_launch(void* const* d_in, const int* in_sizes, int n_in,
                              void* d_out, int out_size) {
    const float* a = (const float*)d_in[0];
    const float* w = (const float*)d_in[1];
    if (n_in >= 2 && in_sizes[0] < in_sizes[1]) {
        const float* t = a; a = w; w = t;
    }

    {
        int total = NA4 + NW4;
        cvt_kernel<<<(total + 255) / 256, 256>>>((const float4*)a, (const float4*)w);
    }

    static bool attr_set = false;
    if (!attr_set) {
        cudaFuncSetAttribute(binlinear_gemm_kernel,
                             cudaFuncAttributeMaxDynamicSharedMemorySize, SMEM_BYTES);
        attr_set = true;
    }
    dim3 grid(DN / TN, DM / TM);   // (16, 64)
    binlinear_gemm_kernel<<<grid, 256, SMEM_BYTES>>>((float*)d_out);
}

// round 10
// speedup vs baseline: 1.8979x; 1.8979x over previous
#include <cuda_runtime.h>
#include <cstdint>

// Problem dims
#define DM 8192
#define DK 2048
#define DN 2048

// GEMM tiling: CTA 128x128, 8 warps in 4(M) x 2(N), warp tile 32x64. 2 CTAs/SM.
constexpr int TM = 128;
constexpr int TN = 128;
constexpr int TKC = 128;           // K bytes per pipeline stage (4 ks sub-chunks)
constexpr int ST = 3;              // pipeline stages
constexpr int NK = DK / TKC;       // 16 chunks

constexpr int ROWB = 144;          // 128 data + 16 pad -> conflict-free ldmatrix
constexpr int A_ST = TM * ROWB;    // 18432
constexpr int B_ST = TN * ROWB;    // 18432
constexpr int STAGE = A_ST + B_ST; // 36864

// smem header: full[ST] mbarriers @0, empty[ST] @32, data @128
constexpr uint32_t OFF_FULL = 0;
constexpr uint32_t OFF_EMPTY = 32;
constexpr uint32_t SMEM_DATA = 128;
constexpr int SMEM_BYTES = SMEM_DATA + ST * STAGE;  // 110720 -> 2 CTAs/SM

// s8 scratch (allocation-free __device__ globals)
__device__ int8_t g_A[(size_t)DM * DK];
__device__ int8_t g_B[(size_t)DN * DK];

// ---------------- helpers ----------------
__device__ __forceinline__ uint32_t smem_u32(const void* p) {
    uint32_t a;
    asm("{ .reg .u64 t; cvta.to.shared.u64 t, %1; cvt.u32.u64 %0, t; }" : "=r"(a) : "l"(p));
    return a;
}

__device__ __forceinline__ void ldm_x4(uint32_t* r, uint32_t addr) {
    asm volatile("ldmatrix.sync.aligned.m8n8.x4.shared.b16 {%0,%1,%2,%3}, [%4];"
                 : "=r"(r[0]), "=r"(r[1]), "=r"(r[2]), "=r"(r[3]) : "r"(addr));
}

#define CP_ASYNC16(dst_u32, src_ptr) \
    asm volatile("cp.async.cg.shared.global [%0], [%1], 16;" \
                 :: "r"((uint32_t)(dst_u32)), "l"(src_ptr) : "memory")

// mbarrier primitives
#define MBARRIER_INIT(addr, count) \
    asm volatile("mbarrier.init.shared.b64 [%0], %1;" :: "r"((uint32_t)(addr)), "r"((uint32_t)(count)) : "memory")
#define MBARRIER_ARRIVE(addr) \
    asm volatile("mbarrier.arrive.shared.b64 _, [%0];" :: "r"((uint32_t)(addr)) : "memory")
// .noinc: completion of this thread's prior cp.asyncs performs ONE arrival that
// counts against the init() expected count (default form nets to zero -> deadlock).
#define CP_ASYNC_MBAR_ARRIVE_NOINC(addr) \
    asm volatile("cp.async.mbarrier.arrive.noinc.shared::cta.b64 [%0];" :: "r"((uint32_t)(addr)) : "memory")

#define MBARRIER_WAIT_PARITY(mbar_smem_addr, phase_parity) do { \
    uint32_t _mbar = (uint32_t)(mbar_smem_addr); \
    uint32_t _parity = (uint32_t)(phase_parity); \
    uint32_t _done; \
    asm volatile( \
        "{\n\t.reg .pred p;\n\t" \
        "mbarrier.try_wait.parity.acquire.cta.shared::cta.b64 p, [%1], %2;\n\t" \
        "selp.b32 %0, 1, 0, p;\n\t}" \
        : "=r"(_done) : "r"(_mbar), "r"(_parity) : "memory"); \
    if (!_done) { \
        asm volatile( \
            "{\n\t.reg .pred P1;\n\t" \
            "WAIT_LOOP_%=:\n\t" \
            "mbarrier.try_wait.parity.acquire.cta.shared::cta.b64 P1, [%0], %1, 0x989680;\n\t" \
            "@P1 bra.uni WAIT_DONE_%=;\n\t" \
            "bra.uni WAIT_LOOP_%=;\n\t" \
            "WAIT_DONE_%=:\n\t}" \
            :: "r"(_mbar), "r"(_parity) : "memory"); \
    } \
} while (0)

// s8 MMA: D(16x8,s32) += A(16x32,s8 row) * B(32x8,s8 col)
#define MMA_S8(C, A, B0, B1) \
    asm volatile("mma.sync.aligned.m16n8k32.row.col.s32.s8.s8.s32 " \
        "{%0,%1,%2,%3}, {%4,%5,%6,%7}, {%8,%9}, {%0,%1,%2,%3};" \
        : "+r"((C)[0]), "+r"((C)[1]), "+r"((C)[2]), "+r"((C)[3]) \
        : "r"((A)[0]), "r"((A)[1]), "r"((A)[2]), "r"((A)[3]), \
          "r"(B0), "r"(B1))

__device__ __forceinline__ float isgn(int v) {
    return (v > 0) ? 1.0f : ((v < 0) ? -1.0f : 0.0f);
}

// ---------------- conversion: fp32 (+-1) -> s8 (+-1), both tensors in one launch ----
constexpr int NA4 = DM * DK / 4;
constexpr int NW4 = DN * DK / 4;
__global__ void cvt_kernel(const float4* __restrict__ a, const float4* __restrict__ w) {
    int i = blockIdx.x * blockDim.x + threadIdx.x;
    const float4* src;
    uint32_t* dst;
    int idx;
    if (i < NA4) {
        src = a; dst = reinterpret_cast<uint32_t*>(g_A); idx = i;
    } else {
        idx = i - NA4;
        if (idx >= NW4) return;
        src = w; dst = reinterpret_cast<uint32_t*>(g_B);
    }
    float4 v = src[idx];
    uint32_t p = (uint32_t)(uint8_t)(int8_t)(v.x > 0.0f ? 1 : -1)
               | ((uint32_t)(uint8_t)(int8_t)(v.y > 0.0f ? 1 : -1) << 8)
               | ((uint32_t)(uint8_t)(int8_t)(v.z > 0.0f ? 1 : -1) << 16)
               | ((uint32_t)(uint8_t)(int8_t)(v.w > 0.0f ? 1 : -1) << 24);
    dst[idx] = p;
}

// ---------------- GEMM + sign kernel ----------------
__global__ void __launch_bounds__(256, 2) binlinear_gemm_kernel(float* __restrict__ out) {
    extern __shared__ int8_t smem[];
    const uint32_t sb = smem_u32(smem);
    const int tid = threadIdx.x;
    const int wid = tid >> 5;
    const int lane = tid & 31;
    const int g = lane >> 2;      // 0..7
    const int tig = lane & 3;     // 0..3
    const int m0 = blockIdx.y * TM;
    const int n0 = blockIdx.x * TN;
    const int wm = (wid & 3) * 32;     // warp M offset
    const int wn = (wid >> 2) * 64;    // warp N offset

    if (tid == 0) {
        #pragma unroll
        for (int s = 0; s < ST; ++s) {
            MBARRIER_INIT(sb + OFF_FULL + s * 8, 256);  // one noinc cp-async arrive per thread
            MBARRIER_INIT(sb + OFF_EMPTY + s * 8, 8);   // one arrive per warp
        }
    }
    __syncthreads();

    // ldmatrix per-lane address offsets (verified: ROWB=144 -> conflict-free)
    const uint32_t aoff = (uint32_t)(wm + (lane & 15)) * ROWB + ((lane >> 4) << 4);
    const uint32_t boff = (uint32_t)(wn + (lane >> 4) * 8 + (lane & 7)) * ROWB
                        + ((lane & 8) << 1);

    int c[2][8][4];
    #pragma unroll
    for (int mt = 0; mt < 2; ++mt)
        #pragma unroll
        for (int nt = 0; nt < 8; ++nt)
            #pragma unroll
            for (int r = 0; r < 4; ++r) c[mt][nt][r] = 0;

    const int8_t* gAbase = g_A + (size_t)m0 * DK;
    const int8_t* gBbase = g_B + (size_t)n0 * DK;

    // per stage: A = 1024 16B-chunks (4/thread), B same; then arm full[s]
    auto produce = [&](int s, int kc) {
        const uint32_t Ab = sb + SMEM_DATA + s * STAGE;
        const uint32_t Bb = Ab + A_ST;
        const int8_t* gA = gAbase + kc * TKC;
        const int8_t* gB = gBbase + kc * TKC;
        #pragma unroll
        for (int h = 0; h < 4; ++h) {
            int ch = tid + h * 256;
            int row = ch >> 3, seg = ch & 7;
            CP_ASYNC16(Ab + row * ROWB + seg * 16, gA + (size_t)row * DK + seg * 16);
        }
        #pragma unroll
        for (int h = 0; h < 4; ++h) {
            int ch = tid + h * 256;
            int row = ch >> 3, seg = ch & 7;
            CP_ASYNC16(Bb + row * ROWB + seg * 16, gB + (size_t)row * DK + seg * 16);
        }
        CP_ASYNC_MBAR_ARRIVE_NOINC(sb + OFF_FULL + s * 8);
    };

    // producer cursor (phase 1: first empty-wait passes on a fresh barrier); consumer cursor
    int pst = 0, pph = 1;
    int cst = 0, cph = 0;

    // prologue: fill ST-1 stages
    #pragma unroll
    for (int s = 0; s < ST - 1; ++s) {
        MBARRIER_WAIT_PARITY(sb + OFF_EMPTY + pst * 8, pph);
        produce(pst, s);
        if (++pst == ST) { pst = 0; pph ^= 1; }
    }

    for (int i = 0; i < NK; ++i) {
        // produce chunk i+ST-1 (if any); its stage was released by this thread at chunk i-1
        if (i + ST - 1 < NK) {
            MBARRIER_WAIT_PARITY(sb + OFF_EMPTY + pst * 8, pph);
            produce(pst, i + ST - 1);
            if (++pst == ST) { pst = 0; pph ^= 1; }
        }

        // consume stage cst
        MBARRIER_WAIT_PARITY(sb + OFF_FULL + cst * 8, cph);
        const uint32_t Ab = sb + SMEM_DATA + cst * STAGE;
        const uint32_t Bb = Ab + A_ST;
        #pragma unroll
        for (int ks = 0; ks < 4; ++ks) {
            const int k0 = ks * 32;
            uint32_t a[2][4];
            ldm_x4(a[0], Ab + aoff + k0);
            ldm_x4(a[1], Ab + aoff + 16 * ROWB + k0);
            #pragma unroll
            for (int p = 0; p < 4; ++p) {
                uint32_t t[4];
                ldm_x4(t, Bb + boff + p * 16 * ROWB + k0);
                MMA_S8(c[0][2 * p + 0], a[0], t[0], t[1]);
                MMA_S8(c[0][2 * p + 1], a[0], t[2], t[3]);
                MMA_S8(c[1][2 * p + 0], a[1], t[0], t[1]);
                MMA_S8(c[1][2 * p + 1], a[1], t[2], t[3]);
            }
        }
        __syncwarp();
        if (lane == 0) MBARRIER_ARRIVE(sb + OFF_EMPTY + cst * 8);
        if (++cst == ST) { cst = 0; cph ^= 1; }
    }

    // ---- epilogue: sign -> float, 8B vectorized stores ----
    #pragma unroll
    for (int mt = 0; mt < 2; ++mt) {
        const int row0 = m0 + wm + mt * 16 + g;
        float* o0 = out + (size_t)row0 * DN + n0 + wn;
        float* o1 = out + (size_t)(row0 + 8) * DN + n0 + wn;
        #pragma unroll
        for (int nt = 0; nt < 8; ++nt) {
            const int col = nt * 8 + tig * 2;
            float2 v0 = make_float2(isgn(c[mt][nt][0]), isgn(c[mt][nt][1]));
            float2 v1 = make_float2(isgn(c[mt][nt][2]), isgn(c[mt][nt][3]));
            *reinterpret_cast<float2*>(o0 + col) = v0;
            *reinterpret_cast<float2*>(o1 + col) = v1;
        }
    }
}

// ---------------- launch ----------------
extern "C" void kernel_launch(void* const* d_in, const int* in_sizes, int n_in,
                              void* d_out, int out_size) {
    const float* a = (const float*)d_in[0];
    const float* w = (const float*)d_in[1];
    if (n_in >= 2 && in_sizes[0] < in_sizes[1]) {
        const float* t = a; a = w; w = t;
    }

    {
        int total = NA4 + NW4;
        cvt_kernel<<<(total + 255) / 256, 256>>>((const float4*)a, (const float4*)w);
    }

    static bool attr_set = false;
    if (!attr_set) {
        cudaFuncSetAttribute(binlinear_gemm_kernel,
                             cudaFuncAttributeMaxDynamicSharedMemorySize, SMEM_BYTES);
        attr_set = true;
    }
    dim3 grid(DN / TN, DM / TM);   // (16, 64)
    binlinear_gemm_kernel<<<grid, 256, SMEM_BYTES>>>((float*)d_out);
}

// round 11
// speedup vs baseline: 1.9150x; 1.0090x over previous
#include <cuda_runtime.h>
#include <cstdint>

// Problem dims
#define DM 8192
#define DK 2048
#define DN 2048

// GEMM tiling: CTA 128x128, 8 warps in 4(M) x 2(N), warp tile 32x64. 2 CTAs/SM.
constexpr int TM = 128;
constexpr int TN = 128;
constexpr int TKC = 128;           // K bytes per pipeline stage (4 ks sub-chunks)
constexpr int ST = 3;              // pipeline stages
constexpr int NK = DK / TKC;       // 16 chunks

constexpr int ROWB = 144;          // 128 data + 16 pad -> conflict-free ldmatrix
constexpr int A_ST = TM * ROWB;    // 18432
constexpr int B_ST = TN * ROWB;    // 18432
constexpr int STAGE = A_ST + B_ST; // 36864

// smem header: full[ST] mbarriers @0, empty[ST] @32, data @128
constexpr uint32_t OFF_FULL = 0;
constexpr uint32_t OFF_EMPTY = 32;
constexpr uint32_t SMEM_DATA = 128;
constexpr int SMEM_BYTES = SMEM_DATA + ST * STAGE;  // 110720 -> 2 CTAs/SM

// s8 scratch (allocation-free __device__ globals)
__device__ int8_t g_A[(size_t)DM * DK];
__device__ int8_t g_B[(size_t)DN * DK];

// ---------------- helpers ----------------
__device__ __forceinline__ uint32_t smem_u32(const void* p) {
    uint32_t a;
    asm("{ .reg .u64 t; cvta.to.shared.u64 t, %1; cvt.u32.u64 %0, t; }" : "=r"(a) : "l"(p));
    return a;
}

__device__ __forceinline__ void ldm_x4(uint32_t* r, uint32_t addr) {
    asm volatile("ldmatrix.sync.aligned.m8n8.x4.shared.b16 {%0,%1,%2,%3}, [%4];"
                 : "=r"(r[0]), "=r"(r[1]), "=r"(r[2]), "=r"(r[3]) : "r"(addr));
}

#define CP_ASYNC16(dst_u32, src_ptr) \
    asm volatile("cp.async.cg.shared.global [%0], [%1], 16;" \
                 :: "r"((uint32_t)(dst_u32)), "l"(src_ptr) : "memory")

// mbarrier primitives
#define MBARRIER_INIT(addr, count) \
    asm volatile("mbarrier.init.shared.b64 [%0], %1;" :: "r"((uint32_t)(addr)), "r"((uint32_t)(count)) : "memory")
#define MBARRIER_ARRIVE(addr) \
    asm volatile("mbarrier.arrive.shared.b64 _, [%0];" :: "r"((uint32_t)(addr)) : "memory")
// .noinc: completion of this thread's prior cp.asyncs performs ONE arrival that
// counts against the init() expected count.
#define CP_ASYNC_MBAR_ARRIVE_NOINC(addr) \
    asm volatile("cp.async.mbarrier.arrive.noinc.shared::cta.b64 [%0];" :: "r"((uint32_t)(addr)) : "memory")

#define MBARRIER_WAIT_PARITY(mbar_smem_addr, phase_parity) do { \
    uint32_t _mbar = (uint32_t)(mbar_smem_addr); \
    uint32_t _parity = (uint32_t)(phase_parity); \
    uint32_t _done; \
    asm volatile( \
        "{\n\t.reg .pred p;\n\t" \
        "mbarrier.try_wait.parity.acquire.cta.shared::cta.b64 p, [%1], %2;\n\t" \
        "selp.b32 %0, 1, 0, p;\n\t}" \
        : "=r"(_done) : "r"(_mbar), "r"(_parity) : "memory"); \
    if (!_done) { \
        asm volatile( \
            "{\n\t.reg .pred P1;\n\t" \
            "WAIT_LOOP_%=:\n\t" \
            "mbarrier.try_wait.parity.acquire.cta.shared::cta.b64 P1, [%0], %1, 0x989680;\n\t" \
            "@P1 bra.uni WAIT_DONE_%=;\n\t" \
            "bra.uni WAIT_LOOP_%=;\n\t" \
            "WAIT_DONE_%=:\n\t}" \
            :: "r"(_mbar), "r"(_parity) : "memory"); \
    } \
} while (0)

// s8 MMA: D(16x8,s32) += A(16x32,s8 row) * B(32x8,s8 col)
#define MMA_S8(C, A, B0, B1) \
    asm volatile("mma.sync.aligned.m16n8k32.row.col.s32.s8.s8.s32 " \
        "{%0,%1,%2,%3}, {%4,%5,%6,%7}, {%8,%9}, {%0,%1,%2,%3};" \
        : "+r"((C)[0]), "+r"((C)[1]), "+r"((C)[2]), "+r"((C)[3]) \
        : "r"((A)[0]), "r"((A)[1]), "r"((A)[2]), "r"((A)[3]), \
          "r"(B0), "r"(B1))

__device__ __forceinline__ float isgn(int v) {
    return (v > 0) ? 1.0f : ((v < 0) ? -1.0f : 0.0f);
}

// ---------------- conversion: fp32 (+-1) -> s8 (+-1), both tensors in one launch ----
constexpr int NA4 = DM * DK / 4;
constexpr int NW4 = DN * DK / 4;
__global__ void cvt_kernel(const float4* __restrict__ a, const float4* __restrict__ w) {
    int i = blockIdx.x * blockDim.x + threadIdx.x;
    const float4* src;
    uint32_t* dst;
    int idx;
    if (i < NA4) {
        src = a; dst = reinterpret_cast<uint32_t*>(g_A); idx = i;
    } else {
        idx = i - NA4;
        if (idx >= NW4) return;
        src = w; dst = reinterpret_cast<uint32_t*>(g_B);
    }
    float4 v = src[idx];
    uint32_t p = (uint32_t)(uint8_t)(int8_t)(v.x > 0.0f ? 1 : -1)
               | ((uint32_t)(uint8_t)(int8_t)(v.y > 0.0f ? 1 : -1) << 8)
               | ((uint32_t)(uint8_t)(int8_t)(v.z > 0.0f ? 1 : -1) << 16)
               | ((uint32_t)(uint8_t)(int8_t)(v.w > 0.0f ? 1 : -1) << 24);
    dst[idx] = p;
}

// ---------------- GEMM + sign kernel ----------------
__global__ void __launch_bounds__(256, 2) binlinear_gemm_kernel(float* __restrict__ out) {
    extern __shared__ int8_t smem[];
    const uint32_t sb = smem_u32(smem);
    const int tid = threadIdx.x;
    const int wid = tid >> 5;
    const int lane = tid & 31;
    const int g = lane >> 2;      // 0..7
    const int tig = lane & 3;     // 0..3
    const int m0 = blockIdx.y * TM;
    const int n0 = blockIdx.x * TN;
    const int wm = (wid & 3) * 32;     // warp M offset
    const int wn = (wid >> 2) * 64;    // warp N offset

    if (tid == 0) {
        #pragma unroll
        for (int s = 0; s < ST; ++s) {
            MBARRIER_INIT(sb + OFF_FULL + s * 8, 256);  // one noinc cp-async arrive per thread
            MBARRIER_INIT(sb + OFF_EMPTY + s * 8, 8);   // one arrive per warp
        }
    }
    __syncthreads();

    // ldmatrix per-lane address offsets (verified: ROWB=144 -> conflict-free)
    const uint32_t aoff = (uint32_t)(wm + (lane & 15)) * ROWB + ((lane >> 4) << 4);
    const uint32_t boff = (uint32_t)(wn + (lane >> 4) * 8 + (lane & 7)) * ROWB
                        + ((lane & 8) << 1);

    int c[2][8][4];
    #pragma unroll
    for (int mt = 0; mt < 2; ++mt)
        #pragma unroll
        for (int nt = 0; nt < 8; ++nt)
            #pragma unroll
            for (int r = 0; r < 4; ++r) c[mt][nt][r] = 0;

    const int8_t* gAbase = g_A + (size_t)m0 * DK;
    const int8_t* gBbase = g_B + (size_t)n0 * DK;

    // per stage: A = 1024 16B-chunks (4/thread), B same; then arm full[s]
    auto produce = [&](int s, int kc) {
        const uint32_t Ab = sb + SMEM_DATA + s * STAGE;
        const uint32_t Bb = Ab + A_ST;
        const int8_t* gA = gAbase + kc * TKC;
        const int8_t* gB = gBbase + kc * TKC;
        #pragma unroll
        for (int h = 0; h < 4; ++h) {
            int ch = tid + h * 256;
            int row = ch >> 3, seg = ch & 7;
            CP_ASYNC16(Ab + row * ROWB + seg * 16, gA + (size_t)row * DK + seg * 16);
        }
        #pragma unroll
        for (int h = 0; h < 4; ++h) {
            int ch = tid + h * 256;
            int row = ch >> 3, seg = ch & 7;
            CP_ASYNC16(Bb + row * ROWB + seg * 16, gB + (size_t)row * DK + seg * 16);
        }
        CP_ASYNC_MBAR_ARRIVE_NOINC(sb + OFF_FULL + s * 8);
    };

    // producer cursor (phase 1: first empty-wait passes on a fresh barrier); consumer cursor
    int pst = 0, pph = 1;
    int cst = 0, cph = 0;

    // prologue: fill ST-1 stages
    #pragma unroll
    for (int s = 0; s < ST - 1; ++s) {
        MBARRIER_WAIT_PARITY(sb + OFF_EMPTY + pst * 8, pph);
        produce(pst, s);
        if (++pst == ST) { pst = 0; pph ^= 1; }
    }

    for (int i = 0; i < NK; ++i) {
        // produce chunk i+ST-1 (if any); its stage was released by this thread at chunk i-1
        if (i + ST - 1 < NK) {
            MBARRIER_WAIT_PARITY(sb + OFF_EMPTY + pst * 8, pph);
            produce(pst, i + ST - 1);
            if (++pst == ST) { pst = 0; pph ^= 1; }
        }

        // consume stage cst, software-pipelined fragments:
        //   bt double-buffer: B(ks,p+1) loads ahead of MMAs on bt(p); at p==3 prefetch B(ks+1,0)
        //   a reloaded right after its last consuming MMA group is issued (WAR via scoreboard)
        MBARRIER_WAIT_PARITY(sb + OFF_FULL + cst * 8, cph);
        const uint32_t Ab = sb + SMEM_DATA + cst * STAGE;
        const uint32_t Bb = Ab + A_ST;

        uint32_t a[2][4];
        uint32_t bt[2][4];
        ldm_x4(a[0], Ab + aoff);
        ldm_x4(a[1], Ab + aoff + 16 * ROWB);
        ldm_x4(bt[0], Bb + boff);             // B(ks=0, p=0)

        #pragma unroll
        for (int ks = 0; ks < 4; ++ks) {
            const int k0 = ks * 32;
            #pragma unroll
            for (int p = 0; p < 4; ++p) {
                uint32_t* cur = bt[p & 1];
                uint32_t* nxt = bt[(p + 1) & 1];
                if (p < 3) {
                    ldm_x4(nxt, Bb + boff + (p + 1) * 16 * ROWB + k0);
                } else if (ks < 3) {
                    ldm_x4(nxt, Bb + boff + (ks + 1) * 32);   // B(ks+1, p=0)
                }
                MMA_S8(c[0][2 * p + 0], a[0], cur[0], cur[1]);
                MMA_S8(c[0][2 * p + 1], a[0], cur[2], cur[3]);
                MMA_S8(c[1][2 * p + 0], a[1], cur[0], cur[1]);
                MMA_S8(c[1][2 * p + 1], a[1], cur[2], cur[3]);
            }
            if (ks < 3) {                      // reload A for next ks (after last use issued)
                ldm_x4(a[0], Ab + aoff + (ks + 1) * 32);
                ldm_x4(a[1], Ab + aoff + 16 * ROWB + (ks + 1) * 32);
            }
        }
        __syncwarp();
        if (lane == 0) MBARRIER_ARRIVE(sb + OFF_EMPTY + cst * 8);
        if (++cst == ST) { cst = 0; cph ^= 1; }
    }

    // ---- epilogue: sign -> float, 8B vectorized stores ----
    #pragma unroll
    for (int mt = 0; mt < 2; ++mt) {
        const int row0 = m0 + wm + mt * 16 + g;
        float* o0 = out + (size_t)row0 * DN + n0 + wn;
        float* o1 = out + (size_t)(row0 + 8) * DN + n0 + wn;
        #pragma unroll
        for (int nt = 0; nt < 8; ++nt) {
            const int col = nt * 8 + tig * 2;
            float2 v0 = make_float2(isgn(c[mt][nt][0]), isgn(c[mt][nt][1]));
            float2 v1 = make_float2(isgn(c[mt][nt][2]), isgn(c[mt][nt][3]));
            *reinterpret_cast<float2*>(o0 + col) = v0;
            *reinterpret_cast<float2*>(o1 + col) = v1;
        }
    }
}

// ---------------- launch ----------------
extern "C" void kernel_launch(void* const* d_in, const int* in_sizes, int n_in,
                              void* d_out, int out_size) {
    const float* a = (const float*)d_in[0];
    const float* w = (const float*)d_in[1];
    if (n_in >= 2 && in_sizes[0] < in_sizes[1]) {
        const float* t = a; a = w; w = t;
    }

    {
        int total = NA4 + NW4;
        cvt_kernel<<<(total + 255) / 256, 256>>>((const float4*)a, (const float4*)w);
    }

    static bool attr_set = false;
    if (!attr_set) {
        cudaFuncSetAttribute(binlinear_gemm_kernel,
                             cudaFuncAttributeMaxDynamicSharedMemorySize, SMEM_BYTES);
        attr_set = true;
    }
    dim3 grid(DN / TN, DM / TM);   // (16, 64)
    binlinear_gemm_kernel<<<grid, 256, SMEM_BYTES>>>((float*)d_out);
}

// round 12
// speedup vs baseline: 2.1380x; 1.1165x over previous
#include <cuda_runtime.h>
#include <cstdint>

// Problem dims
#define DM 8192
#define DK 2048
#define DN 2048

// GEMM tiling: CTA 128x128, 8 warps in 4(M) x 2(N), warp tile 32x64. 2 CTAs/SM.
constexpr int TM = 128;
constexpr int TN = 128;
constexpr int TKC = 128;           // K bytes per stage (4 ks sub-chunks)
constexpr int ST = 3;              // pipeline stages
constexpr int NK = DK / TKC;       // 16 chunks

// Tile-contiguous, pre-swizzled operand layout:
//   g_A2[mblk][kc][row 0..127][col 0..127 ^ ((row&7)<<4)]   (16 KB tiles)
//   g_B2[nblk][kc][row 0..127][col swizzled]
constexpr int TILE_BYTES = 128 * 128;          // 16384
constexpr int A_ST = TILE_BYTES;
constexpr int STAGE = 2 * TILE_BYTES;          // A + B = 32768

// smem header: full[ST] mbarriers @0, empty[ST] @32, data @128
constexpr uint32_t OFF_FULL = 0;
constexpr uint32_t OFF_EMPTY = 32;
constexpr uint32_t SMEM_DATA = 128;
constexpr int SMEM_BYTES = SMEM_DATA + ST * STAGE;   // 98432 -> 2 CTAs/SM

// s8 scratch (allocation-free __device__ globals)
__device__ int8_t g_A2[(size_t)DM * DK];
__device__ int8_t g_B2[(size_t)DN * DK];

// ---------------- helpers ----------------
__device__ __forceinline__ uint32_t smem_u32(const void* p) {
    uint32_t a;
    asm("{ .reg .u64 t; cvta.to.shared.u64 t, %1; cvt.u32.u64 %0, t; }" : "=r"(a) : "l"(p));
    return a;
}

__device__ __forceinline__ void ldm_x4(uint32_t* r, uint32_t addr) {
    asm volatile("ldmatrix.sync.aligned.m8n8.x4.shared.b16 {%0,%1,%2,%3}, [%4];"
                 : "=r"(r[0]), "=r"(r[1]), "=r"(r[2]), "=r"(r[3]) : "r"(addr));
}

// mbarrier primitives
#define MBARRIER_INIT(addr, count) \
    asm volatile("mbarrier.init.shared.b64 [%0], %1;" :: "r"((uint32_t)(addr)), "r"((uint32_t)(count)) : "memory")
#define MBARRIER_ARRIVE(addr) \
    asm volatile("mbarrier.arrive.shared.b64 _, [%0];" :: "r"((uint32_t)(addr)) : "memory")
#define MBARRIER_EXPECT_TX(addr, bytes) \
    asm volatile("mbarrier.arrive.expect_tx.shared.b64 _, [%0], %1;" :: "r"((uint32_t)(addr)), "r"((uint32_t)(bytes)) : "memory")

// 1D bulk copy gmem->smem with transaction-count completion (sm_90 baseline)
#define CP_BULK_G2S(dst_u32, src_ptr, bytes, mbar_u32) \
    asm volatile("cp.async.bulk.shared::cluster.global.mbarrier::complete_tx::bytes [%0], [%1], %2, [%3];" \
                 :: "r"((uint32_t)(dst_u32)), "l"(src_ptr), "r"((uint32_t)(bytes)), "r"((uint32_t)(mbar_u32)) : "memory")

#define MBARRIER_WAIT_PARITY(mbar_smem_addr, phase_parity) do { \
    uint32_t _mbar = (uint32_t)(mbar_smem_addr); \
    uint32_t _parity = (uint32_t)(phase_parity); \
    uint32_t _done; \
    asm volatile( \
        "{\n\t.reg .pred p;\n\t" \
        "mbarrier.try_wait.parity.acquire.cta.shared::cta.b64 p, [%1], %2;\n\t" \
        "selp.b32 %0, 1, 0, p;\n\t}" \
        : "=r"(_done) : "r"(_mbar), "r"(_parity) : "memory"); \
    if (!_done) { \
        asm volatile( \
            "{\n\t.reg .pred P1;\n\t" \
            "WAIT_LOOP_%=:\n\t" \
            "mbarrier.try_wait.parity.acquire.cta.shared::cta.b64 P1, [%0], %1, 0x989680;\n\t" \
            "@P1 bra.uni WAIT_DONE_%=;\n\t" \
            "bra.uni WAIT_LOOP_%=;\n\t" \
            "WAIT_DONE_%=:\n\t}" \
            :: "r"(_mbar), "r"(_parity) : "memory"); \
    } \
} while (0)

// s8 MMA: D(16x8,s32) += A(16x32,s8 row) * B(32x8,s8 col)
#define MMA_S8(C, A, B0, B1) \
    asm volatile("mma.sync.aligned.m16n8k32.row.col.s32.s8.s8.s32 " \
        "{%0,%1,%2,%3}, {%4,%5,%6,%7}, {%8,%9}, {%0,%1,%2,%3};" \
        : "+r"((C)[0]), "+r"((C)[1]), "+r"((C)[2]), "+r"((C)[3]) \
        : "r"((A)[0]), "r"((A)[1]), "r"((A)[2]), "r"((A)[3]), \
          "r"(B0), "r"(B1))

__device__ __forceinline__ float isgn(int v) {
    return (v > 0) ? 1.0f : ((v < 0) ? -1.0f : 0.0f);
}

// ---------------- conversion: fp32 (+-1) -> pre-swizzled tile-contiguous s8 ----------------
// Output word o (4 bytes) lives at tile=o>>12, row=(o>>5)&127, wcol=o&31.
// Its bytes must hold sign(X[blk*128+row][kc*128 + (wcol*4 ^ ((row&7)<<4)) .. +3]).
constexpr int NA4 = DM * DK / 4;   // output words for A
constexpr int NW4 = DN * DK / 4;   // output words for B
__global__ void cvt_kernel(const float4* __restrict__ a, const float4* __restrict__ w) {
    int i = blockIdx.x * blockDim.x + threadIdx.x;
    const float4* src;
    uint32_t* dst;
    int o;
    if (i < NA4) {
        src = a; dst = reinterpret_cast<uint32_t*>(g_A2); o = i;
    } else {
        o = i - NA4;
        if (o >= NW4) return;
        src = w; dst = reinterpret_cast<uint32_t*>(g_B2);
    }
    int tile = o >> 12;             // 4096 words per 16KB tile
    int wi = o & 4095;
    int row = wi >> 5;              // 0..127
    int wcol = wi & 31;             // word within row
    int col_byte = (wcol * 4) ^ ((row & 7) << 4);
    int blk = tile >> 4;            // m-block or n-block
    int kc = tile & 15;
    // input float index: (blk*128+row)*2048 + kc*128 + col_byte ; float4 index = /4
    int f4 = (((blk * 128 + row) * 2048) + kc * 128 + col_byte) >> 2;
    float4 v = src[f4];
    uint32_t p = (uint32_t)(uint8_t)(int8_t)(v.x > 0.0f ? 1 : -1)
               | ((uint32_t)(uint8_t)(int8_t)(v.y > 0.0f ? 1 : -1) << 8)
               | ((uint32_t)(uint8_t)(int8_t)(v.z > 0.0f ? 1 : -1) << 16)
               | ((uint32_t)(uint8_t)(int8_t)(v.w > 0.0f ? 1 : -1) << 24);
    dst[o] = p;
}

// ---------------- GEMM + sign kernel ----------------
__global__ void __launch_bounds__(256, 2) binlinear_gemm_kernel(float* __restrict__ out) {
    extern __shared__ int8_t smem[];
    const uint32_t sb = smem_u32(smem);
    const int tid = threadIdx.x;
    const int wid = tid >> 5;
    const int lane = tid & 31;
    const int g = lane >> 2;      // 0..7
    const int tig = lane & 3;     // 0..3
    const int mblk = blockIdx.y;
    const int nblk = blockIdx.x;
    const int m0 = mblk * TM;
    const int n0 = nblk * TN;
    const int wm = (wid & 3) * 32;     // warp M offset
    const int wn = (wid >> 2) * 64;    // warp N offset

    if (tid == 0) {
        #pragma unroll
        for (int s = 0; s < ST; ++s) {
            MBARRIER_INIT(sb + OFF_FULL + s * 8, 1);    // one expect_tx arrive + 32KB tx
            MBARRIER_INIT(sb + OFF_EMPTY + s * 8, 8);   // one arrive per warp
        }
    }
    __syncthreads();

    // per-lane ldmatrix bases in the swizzled 128B-row layout
    const int rowA0 = wm + (lane & 15);
    const uint32_t aRow0 = (uint32_t)rowA0 * 128;
    const uint32_t aRow1 = aRow0 + 16 * 128;
    const uint32_t swzA = (uint32_t)(rowA0 & 7) << 4;
    const uint32_t asegb = (uint32_t)(lane >> 4) << 4;       // 0 or 16

    const int rowB = wn + (lane >> 4) * 8 + (lane & 7);
    const uint32_t bRow = (uint32_t)rowB * 128;
    const uint32_t swzB = (uint32_t)(rowB & 7) << 4;
    const uint32_t bsegb = (uint32_t)(lane & 8) << 1;        // 0 or 16

    int c[2][8][4];
    #pragma unroll
    for (int mt = 0; mt < 2; ++mt)
        #pragma unroll
        for (int nt = 0; nt < 8; ++nt)
            #pragma unroll
            for (int r = 0; r < 4; ++r) c[mt][nt][r] = 0;

    const int8_t* gA = g_A2 + (size_t)(mblk * 16) * TILE_BYTES;  // + kc*16KB
    const int8_t* gB = g_B2 + (size_t)(nblk * 16) * TILE_BYTES;

    // cursors (identical discipline to the verified ring)
    int pst = 0, pph = 1;
    int cst = 0, cph = 0;

    // prologue: tid0 arms stages 0..ST-2
    if (tid == 0) {
        #pragma unroll
        for (int s = 0; s < ST - 1; ++s) {
            const uint32_t full = sb + OFF_FULL + s * 8;
            MBARRIER_EXPECT_TX(full, STAGE);
            const uint32_t Ab = sb + SMEM_DATA + s * STAGE;
            CP_BULK_G2S(Ab, gA + (size_t)s * TILE_BYTES, TILE_BYTES, full);
            CP_BULK_G2S(Ab + A_ST, gB + (size_t)s * TILE_BYTES, TILE_BYTES, full);
        }
    }
    pst = ST - 1;  // next produce target (stage 2), phase still 1

    for (int i = 0; i < NK; ++i) {
        // tid0 produces chunk i+ST-1 (stage released by consumers at chunk i-1)
        if (tid == 0 && i + ST - 1 < NK) {
            MBARRIER_WAIT_PARITY(sb + OFF_EMPTY + pst * 8, pph);
            const uint32_t full = sb + OFF_FULL + pst * 8;
            MBARRIER_EXPECT_TX(full, STAGE);
            const uint32_t Ab = sb + SMEM_DATA + pst * STAGE;
            const size_t kc = (size_t)(i + ST - 1) * TILE_BYTES;
            CP_BULK_G2S(Ab, gA + kc, TILE_BYTES, full);
            CP_BULK_G2S(Ab + A_ST, gB + kc, TILE_BYTES, full);
        }
        if (tid == 0) { if (++pst == ST) { pst = 0; pph ^= 1; } }

        // consume stage cst
        MBARRIER_WAIT_PARITY(sb + OFF_FULL + cst * 8, cph);
        const uint32_t Ab = sb + SMEM_DATA + cst * STAGE;
        const uint32_t Bb = Ab + A_ST;
        #pragma unroll
        for (int ks = 0; ks < 4; ++ks) {
            const uint32_t k0 = (uint32_t)ks * 32;
            uint32_t a[2][4];
            ldm_x4(a[0], Ab + aRow0 + ((asegb + k0) ^ swzA));
            ldm_x4(a[1], Ab + aRow1 + ((asegb + k0) ^ swzA));
            #pragma unroll
            for (int p = 0; p < 4; ++p) {
                uint32_t t[4];
                ldm_x4(t, Bb + bRow + (uint32_t)p * 2048 + ((bsegb + k0) ^ swzB));
                MMA_S8(c[0][2 * p + 0], a[0], t[0], t[1]);
                MMA_S8(c[0][2 * p + 1], a[0], t[2], t[3]);
                MMA_S8(c[1][2 * p + 0], a[1], t[0], t[1]);
                MMA_S8(c[1][2 * p + 1], a[1], t[2], t[3]);
            }
        }
        __syncwarp();
        if (lane == 0) MBARRIER_ARRIVE(sb + OFF_EMPTY + cst * 8);
        if (++cst == ST) { cst = 0; cph ^= 1; }
    }

    // ---- epilogue: sign -> float, 8B vectorized stores ----
    #pragma unroll
    for (int mt = 0; mt < 2; ++mt) {
        const int row0 = m0 + wm + mt * 16 + g;
        float* o0 = out + (size_t)row0 * DN + n0 + wn;
        float* o1 = out + (size_t)(row0 + 8) * DN + n0 + wn;
        #pragma unroll
        for (int nt = 0; nt < 8; ++nt) {
            const int col = nt * 8 + tig * 2;
            float2 v0 = make_float2(isgn(c[mt][nt][0]), isgn(c[mt][nt][1]));
            float2 v1 = make_float2(isgn(c[mt][nt][2]), isgn(c[mt][nt][3]));
            *reinterpret_cast<float2*>(o0 + col) = v0;
            *reinterpret_cast<float2*>(o1 + col) = v1;
        }
    }
}

// ---------------- launch ----------------
extern "C" void kernel_launch(void* const* d_in, const int* in_sizes, int n_in,
                              void* d_out, int out_size) {
    const float* a = (const float*)d_in[0];
    const float* w = (const float*)d_in[1];
    if (n_in >= 2 && in_sizes[0] < in_sizes[1]) {
        const float* t = a; a = w; w = t;
    }

    {
        int total = NA4 + NW4;
        cvt_kernel<<<(total + 255) / 256, 256>>>((const float4*)a, (const float4*)w);
    }

    static bool attr_set = false;
    if (!attr_set) {
        cudaFuncSetAttribute(binlinear_gemm_kernel,
                             cudaFuncAttributeMaxDynamicSharedMemorySize, SMEM_BYTES);
        attr_set = true;
    }
    dim3 grid(DN / TN, DM / TM);   // (16, 64)
    binlinear_gemm_kernel<<<grid, 256, SMEM_BYTES>>>((float*)d_out);
}